// round 16
// baseline (speedup 1.0000x reference)
#include <cuda_runtime.h>
#include <cuda_fp16.h>
#include <math.h>
#include <cstdint>

// ---------------- problem constants ----------------
// B=4, C=3, H=W=768, P=128, S=64, K=31, n_h=n_w=11, N=121
#define TOTAL   7077888
#define IMGHW   589824
#define NPIX    961

// ---------------- device scratch ----------------
__device__ float g_basis[14 * NPIX];      // rms-normalized basis (constants)
__device__ float g_mask[NPIX];
__device__ float g_coeffs[121 * 14];
__device__ float g_kern[363 * NPIX];      // flipped+normalized PSFs
__device__ float g_xlin[TOTAL];           // (relu(x)+eps)^gamma
__device__ float g_acc[4 * TOTAL];        // 4 parity planes (zero .bss; only valid entries written)

__device__ __forceinline__ float hannf(int r) {
    return 0.5f * (1.0f - __cosf((6.28318530717958647692f * (float)r) * 0.0078125f));
}
__device__ __forceinline__ double dpow_i(double x, int e) {
    double r = 1.0;
    for (int q = 0; q < e; q++) r *= x;
    return r;
}
__device__ __forceinline__ __half2 u2h(uint32_t u) {
    return *reinterpret_cast<__half2*>(&u);
}

// ---------------- stage 0a: pupil basis, computed ONCE (1 block) ----------------
// CRITICAL numerics: numpy-exact IEEE sequence (no FMA contraction) — 16 pixels sit
// EXACTLY on r2==1 (9-12-15 triple); membership decided by last-ulp rounding.
__global__ void basis_kernel() {
    __shared__ float red[1024];
    int t = threadIdx.x;
    bool act = (t < NPIX);
    int i = t / 31, j = t % 31;

    double step = 2.0 / 30.0;
    double x = 0.0, y = 0.0;
    float m = 0.0f;
    if (act) {
        x = (j == 30) ? 1.0 : __dadd_rn(__dmul_rn((double)j, step), -1.0);
        y = (i == 30) ? 1.0 : __dadd_rn(__dmul_rn((double)i, step), -1.0);
        double r2 = __dadd_rn(__dmul_rn(x, x), __dmul_rn(y, y));
        m = (r2 <= 1.0) ? 1.0f : 0.0f;
        g_mask[t] = m;
    }
    red[t] = act ? m : 0.0f;
    __syncthreads();
    for (int s = 512; s > 0; s >>= 1) {
        if (t < s) red[t] += red[t + s];
        __syncthreads();
    }
    float mc = red[0];
    __syncthreads();

    int z = 0;
    for (int deg = 1; deg <= 4; deg++) {
        for (int k = 0; k <= deg; k++) {
            float bb = 0.0f;
            if (act) bb = (float)(dpow_i(x, deg - k) * dpow_i(y, k)) * m;
            red[t] = bb * bb;
            __syncthreads();
            for (int s = 512; s > 0; s >>= 1) {
                if (t < s) red[t] += red[t + s];
                __syncthreads();
            }
            float rms = sqrtf(red[0] / mc) + 1e-8f;
            __syncthreads();
            if (act) g_basis[z * NPIX + t] = bb / rms;
            z++;
        }
    }
}

// ---------------- stage 0b: MLP -> zernike coeffs ----------------
__global__ void mlp_kernel(const float* __restrict__ w1, const float* __restrict__ b1,
                           const float* __restrict__ w2, const float* __restrict__ b2,
                           const float* __restrict__ w3, const float* __restrict__ b3) {
    __shared__ float s1[64], s2[64];
    int n = blockIdx.x;
    int t = threadIdx.x;
    int iy = n / 11, jx = n % 11;
    float cy = (float)((((double)(iy * 64) + 64.0) / 768.0) * 2.0 - 1.0);
    float cx = (float)((((double)(jx * 64) + 64.0) / 768.0) * 2.0 - 1.0);

    float h = tanhf(cy * w1[t] + cx * w1[64 + t] + b1[t]);
    s1[t] = h;
    __syncthreads();
    float a = b2[t];
    for (int k = 0; k < 64; k++) a += s1[k] * w2[k * 64 + t];
    s2[t] = tanhf(a);
    __syncthreads();
    if (t < 14) {
        float o = b3[t];
        for (int k = 0; k < 64; k++) o += s2[k] * w3[k * 14 + t];
        g_coeffs[n * 14 + t] = o;
    }
}

// ---------------- stage 0c: PSF via 31x31 separable DFT (one reduction) ----------------
__global__ void psf_kernel() {
    __shared__ float fre[NPIX], fim[NPIX], Gre[NPIX], Gim[NPIX];
    __shared__ float twr[31], twi[31], scoef[14], red[33];
    int t = threadIdx.x;
    bool act = (t < NPIX);
    int blk = blockIdx.x;            // n*3 + c
    int n = blk / 3, c = blk % 3;

    if (t < 31) {
        float ang = -6.28318530717958647692f * (float)t / 31.0f;
        twr[t] = cosf(ang);
        twi[t] = sinf(ang);
    }
    if (t < 14) scoef[t] = g_coeffs[n * 14 + t];
    __syncthreads();

    float wl = 0.53f / ((c == 0) ? 0.61f : ((c == 1) ? 0.53f : 0.47f));
    if (act) {
        float ph = 0.0f;
#pragma unroll
        for (int z = 0; z < 14; z++) ph = fmaf(scoef[z], g_basis[z * NPIX + t], ph);
        float th = 6.28318530717958647692f * (wl * ph);
        float sn, cs;
        sincosf(th, &sn, &cs);
        float m = g_mask[t];
        fre[t] = m * cs;
        fim[t] = m * sn;
    }
    __syncthreads();

    int u = t / 31, v = t % 31;
    if (act) {
        float gr = 0.0f, gi = 0.0f;
        int m2 = 0;
        for (int i2 = 0; i2 < 31; i2++) {
            float tr = twr[m2], ti = twi[m2];
            float ar = fre[i2 * 31 + v], ai = fim[i2 * 31 + v];
            gr = fmaf(ar, tr, gr); gr = fmaf(-ai, ti, gr);
            gi = fmaf(ar, ti, gi); gi = fmaf(ai, tr, gi);
            m2 += u; if (m2 >= 31) m2 -= 31;
        }
        Gre[t] = gr; Gim[t] = gi;
    }
    __syncthreads();

    float mag = 0.0f;
    if (act) {
        float fr = 0.0f, fi = 0.0f;
        int m2 = 0;
        for (int j2 = 0; j2 < 31; j2++) {
            float tr = twr[m2], ti = twi[m2];
            float gr = Gre[u * 31 + j2], gi = Gim[u * 31 + j2];
            fr = fmaf(gr, tr, fr); fr = fmaf(-gi, ti, fr);
            fi = fmaf(gr, ti, fi); fi = fmaf(gi, tr, fi);
            m2 += v; if (m2 >= 31) m2 -= 31;
        }
        mag = fr * fr + fi * fi;
    }
    // one shuffle-based block reduction
    {
        float vsum = act ? mag : 0.0f;
#pragma unroll
        for (int o = 16; o > 0; o >>= 1) vsum += __shfl_down_sync(0xffffffffu, vsum, o);
        int w = t >> 5;
        if ((t & 31) == 0) red[w] = vsum;
        __syncthreads();
        if (t < 32) {
            float r = red[t];
#pragma unroll
            for (int o = 16; o > 0; o >>= 1) r += __shfl_down_sync(0xffffffffu, r, o);
            if (t == 0) red[32] = r;
        }
        __syncthreads();
    }
    float inv = 1.0f / (red[32] + 1e-6f);
    if (act) {
        int pu = u + 15; if (pu >= 31) pu -= 31;   // fftshift
        int pv = v + 15; if (pv >= 31) pv -= 31;
        g_kern[blk * NPIX + (30 - pu) * 31 + (30 - pv)] = mag * inv;  // flip
    }
}

// ---------------- stage 1: gamma-linearize (float4 + fast pow) ----------------
__global__ void prep_kernel(const float4* __restrict__ x, const float* __restrict__ gp) {
    int id = blockIdx.x * blockDim.x + threadIdx.x;
    float g = *gp;
    float4 v = x[id];
    float4 o;
    o.x = __expf(g * __logf(fmaxf(v.x, 0.0f) + 1e-6f));
    o.y = __expf(g * __logf(fmaxf(v.y, 0.0f) + 1e-6f));
    o.z = __expf(g * __logf(fmaxf(v.z, 0.0f) + 1e-6f));
    o.w = __expf(g * __logf(fmaxf(v.w, 0.0f) + 1e-6f));
    ((float4*)g_xlin)[id] = o;
}

// ---------------- stage 2: 31x31 depthwise conv — fp16 HFMA2 mainloop ----------------
// Same even/odd pair algebra as the fp32 champion, but data/taps in half2 (row pairs),
// per-dc fp16 partials (HMUL2 first tap, HFMA2 rest), flushed to fp32 accumulators
// after each dc column (chain length <= 16 keeps fp16 rounding ~3e-4 of output).
// Column stride 84 u32 = 21 x 16B (odd) => LDS.128 conflict-free across the warp.
#define HSTR 84
__global__ void __launch_bounds__(256) conv_kernel() {
    __shared__ __align__(16) __half2 sH[62 * HSTR];   // [col][rowpair], 20.8 KB
    __shared__ __align__(16) __half2 sT[31 * 32];     // taps (k,k), [dc][dr], 4 KB

    int id = blockIdx.x;
    int tile = id & 3;
    int pcc = id >> 2;
    int c = pcc % 3;
    int t2 = pcc / 3;
    int n = t2 % 121;
    int b = t2 / 121;
    int ip = n / 11, jp = n % 11;
    int C0 = tile << 5;          // 0,32,64,96
    int tid = threadIdx.x;

    const float* gk = g_kern + (n * 3 + c) * NPIX;
    for (int q = tid; q < NPIX; q += 256) {
        int dr = q / 31, dcc = q - dr * 31;
        __half h = __float2half_rn(gk[q]);
        sT[dcc * 32 + dr] = __halves2half2(h, h);
    }

    const float* gxp = g_xlin + (size_t)(b * 3 + c) * IMGHW;
    for (int q = tid; q < 79 * 62; q += 256) {
        int rp = q / 62, cc = q - rp * 62;
        int sx = C0 + cc - 15;
        int sy0 = 2 * rp - 15;
        float v0 = 0.0f, v1 = 0.0f;
        if ((unsigned)sx < 128u) {
            const float* g = gxp + (ip * 64 + sy0) * 768 + jp * 64 + sx;
            if ((unsigned)sy0 < 128u)       v0 = g[0];
            if ((unsigned)(sy0 + 1) < 128u) v1 = g[768];
        }
        sH[cc * HSTR + rp] = __floats2half2_rn(v0, v1);
    }
    __syncthreads();

    int tx = tid & 31, ty = tid >> 5;    // ty 0..7 owns rows 16ty..16ty+15 (pairs 8ty..8ty+7)
    float2 A32[8];
    float2 O32[9];
#pragma unroll
    for (int q = 0; q < 8; q++) A32[q] = make_float2(0.0f, 0.0f);
#pragma unroll
    for (int q = 0; q < 9; q++) O32[q] = make_float2(0.0f, 0.0f);

#pragma unroll 1
    for (int dc = 0; dc < 31; ++dc) {
        const uint32_t* colp = (const uint32_t*)(sH + (tx + dc) * HSTR) + ty * 8;
        const uint2* kp = (const uint2*)(sT + dc * 32);
        uint32_t pe[16];
        // preload logical pair entries 0..11 (3x LDS.128)
#pragma unroll
        for (int m2 = 0; m2 < 3; m2++) {
            uint4 w = ((const uint4*)colp)[m2];
            pe[4 * m2] = w.x; pe[4 * m2 + 1] = w.y;
            pe[4 * m2 + 2] = w.z; pe[4 * m2 + 3] = w.w;
        }

        __half2 hA[8], hO[9];
        {
            uint2 kk = kp[0];                 // d = 0: HMUL2 (implicit zero-init)
            __half2 ke = u2h(kk.x), ko = u2h(kk.y);
#pragma unroll
            for (int j = 0; j < 8; j++) hA[j] = __hmul2(ke, u2h(pe[j]));
#pragma unroll
            for (int j = 0; j < 9; j++) hO[j] = __hmul2(ko, u2h(pe[j]));
        }
#pragma unroll
        for (int d = 1; d < 15; d++) {
            if (d == 4 || d == 8 || d == 12) {   // refill logical d+8..d+11
                uint4 w = ((const uint4*)colp)[(d + 8) >> 2];
                pe[(d + 8) & 15] = w.x;  pe[(d + 9) & 15] = w.y;
                pe[(d + 10) & 15] = w.z; pe[(d + 11) & 15] = w.w;
            }
            uint2 kk = kp[d];
            __half2 ke = u2h(kk.x), ko = u2h(kk.y);
#pragma unroll
            for (int j = 0; j < 8; j++) hA[j] = __hfma2(ke, u2h(pe[(d + j) & 15]), hA[j]);
#pragma unroll
            for (int j = 0; j < 9; j++) hO[j] = __hfma2(ko, u2h(pe[(d + j) & 15]), hO[j]);
        }
        {
            // d = 15: even tap dr=30 only; uses logical 15..22 (refilled at d=12: up to 23)
            uint4 w = ((const uint4*)colp)[5];   // logical 20..23
            pe[20 & 15] = w.x; pe[21 & 15] = w.y; pe[22 & 15] = w.z; pe[23 & 15] = w.w;
            uint32_t keu = ((const uint32_t*)kp)[30];
            __half2 ke = u2h(keu);
#pragma unroll
            for (int j = 0; j < 8; j++) hA[j] = __hfma2(ke, u2h(pe[(15 + j) & 15]), hA[j]);
        }

        // flush fp16 column partials into fp32 accumulators
#pragma unroll
        for (int j = 0; j < 8; j++) {
            A32[j].x += __low2float(hA[j]);
            A32[j].y += __high2float(hA[j]);
        }
#pragma unroll
        for (int j = 0; j < 9; j++) {
            O32[j].x += __low2float(hO[j]);
            O32[j].y += __high2float(hO[j]);
        }
    }

    // recombine: out[2j] = A[j].lo + O[j].hi ; out[2j+1] = A[j].hi + O[j+1].lo
    int plane = ((ip & 1) << 1) | (jp & 1);
    float hc = hannf(C0 + tx);
    int gx0 = jp * 64 + C0 + tx;
    float* outp = g_acc + (size_t)plane * TOTAL + (size_t)(b * 3 + c) * IMGHW;
#pragma unroll
    for (int j = 0; j < 8; j++) {
        int pr0 = ty * 16 + 2 * j;
        float o0 = A32[j].x + O32[j].y;
        float o1 = A32[j].y + O32[j + 1].x;
        outp[(ip * 64 + pr0) * 768 + gx0]     = o0 * (hannf(pr0) * hc);
        outp[(ip * 64 + pr0 + 1) * 768 + gx0] = o1 * (hannf(pr0 + 1) * hc);
    }
}

// ---------------- stage 3: gather planes, window-normalize, inverse gamma ----------------
__global__ void fin_kernel(float4* __restrict__ out, const float* __restrict__ gp) {
    int id = blockIdx.x * blockDim.x + threadIdx.x;
    float ig = 1.0f / (*gp);
    int e0 = id * 4;
    int xc0 = e0 % 768;
    int y = (e0 / 768) % 768;

    float ny = 0.0f;
    int i1 = y >> 6;
    if (i1 <= 10) ny += hannf(y - i1 * 64);
    if (i1 >= 1)  ny += hannf(y - (i1 - 1) * 64);

    const float4* a0 = (const float4*)g_acc;
    float4 p0 = a0[id];
    float4 p1 = a0[(TOTAL >> 2) + id];
    float4 p2 = a0[(TOTAL >> 1) + id];
    float4 p3 = a0[3 * (TOTAL >> 2) + id];

    float4 r;
    float* rr = &r.x;
    const float* q0 = &p0.x; const float* q1 = &p1.x;
    const float* q2 = &p2.x; const float* q3 = &p3.x;
#pragma unroll
    for (int k = 0; k < 4; k++) {
        int xcol = xc0 + k;
        float nx = 0.0f;
        int j1 = xcol >> 6;
        if (j1 <= 10) nx += hannf(xcol - j1 * 64);
        if (j1 >= 1)  nx += hannf(xcol - (j1 - 1) * 64);
        float s = q0[k] + q1[k] + q2[k] + q3[k];
        float v = s / (ny * nx + 1e-6f);
        rr[k] = __expf(ig * __logf(fmaxf(v, 0.0f) + 1e-6f));
    }
    out[id] = r;
}

// ---------------- launch ----------------
extern "C" void kernel_launch(void* const* d_in, const int* in_sizes, int n_in,
                              void* d_out, int out_size) {
    const float* x  = (const float*)d_in[0];
    const float* w1 = (const float*)d_in[1];
    const float* b1 = (const float*)d_in[2];
    const float* w2 = (const float*)d_in[3];
    const float* b2 = (const float*)d_in[4];
    const float* w3 = (const float*)d_in[5];
    const float* b3 = (const float*)d_in[6];
    const float* gp = (const float*)d_in[7];

    basis_kernel<<<1, 1024>>>();
    mlp_kernel<<<121, 64>>>(w1, b1, w2, b2, w3, b3);
    psf_kernel<<<363, 1024>>>();
    prep_kernel<<<(TOTAL / 4) / 256, 256>>>((const float4*)x, gp);
    conv_kernel<<<5808, 256>>>();
    fin_kernel<<<(TOTAL / 4) / 256, 256>>>((float4*)d_out, gp);
}